// round 8
// baseline (speedup 1.0000x reference)
#include <cuda_runtime.h>
#include <cuda_fp16.h>
#include <cstdint>

// ---------------- problem constants ----------------
#define NEXP 64
#define DIM  2048
#define HID  1024
#define TOK  16384
#define TPE  256

// scratch: fp16 SwiGLU intermediate + fp16 pre-converted X
__device__ __half g_h[(size_t)TOK * HID];
__device__ __half g_x[(size_t)TOK * DIM];

// ---------------- helpers ----------------
__device__ __forceinline__ uint32_t smem_u32(const void* p) {
    uint32_t a;
    asm("{ .reg .u64 t; cvta.to.shared.u64 t, %1; cvt.u32.u64 %0, t; }" : "=r"(a) : "l"(p));
    return a;
}
__device__ __forceinline__ uint32_t pkh2(float lo, float hi) {
    uint32_t r;
    asm("cvt.rn.f16x2.f32 %0, %1, %2;" : "=r"(r) : "f"(hi), "f"(lo));
    return r;
}

#define SWZ(x) ((x) ^ (((x) >> 3) & 0x70))

__device__ __forceinline__ void cp16(uint32_t dst, const void* src) {
    asm volatile("cp.async.cg.shared.global [%0], [%1], 16;" :: "r"(dst), "l"(src));
}
#define CP_COMMIT() asm volatile("cp.async.commit_group;" ::: "memory")
#define CP_WAIT2()  asm volatile("cp.async.wait_group 2;" ::: "memory")

__device__ __forceinline__ void ldsm4(uint32_t* f, uint32_t addr) {
    asm volatile("ldmatrix.sync.aligned.m8n8.x4.shared.b16 {%0,%1,%2,%3}, [%4];"
                 : "=r"(f[0]), "=r"(f[1]), "=r"(f[2]), "=r"(f[3]) : "r"(addr));
}

__device__ __forceinline__ void mma16(float* d, const uint32_t* a, uint32_t b0, uint32_t b1) {
    asm volatile("mma.sync.aligned.m16n8k16.row.col.f32.f16.f16.f32 "
                 "{%0,%1,%2,%3},{%4,%5,%6,%7},{%8,%9},{%0,%1,%2,%3};"
                 : "+f"(d[0]), "+f"(d[1]), "+f"(d[2]), "+f"(d[3])
                 : "r"(a[0]), "r"(a[1]), "r"(a[2]), "r"(a[3]), "r"(b0), "r"(b1));
}

__device__ __forceinline__ float silu(float v) {
    return v / (1.0f + __expf(-v));
}

// ---------------- smem layout ----------------
// A stages: 4 x 32768B (256 rows x 128B = 64 fp16 k, SW128) at 0.
// B stages: n-major fp16, pitch 144B, at 131072. 18432B/stage both kernels.
#define ABUF_SZ  32768
#define BOFF     131072
#define BSTG     18432
#define SMEM_TOT 204800

// ======================================================================
// Kernel 0: convert X to fp16 once
// ======================================================================
__global__ __launch_bounds__(256)
void preconv_kernel(const float* __restrict__ x)
{
    size_t i = (size_t)(blockIdx.x * 256 + threadIdx.x);
    size_t stride = (size_t)gridDim.x * 256;
    const size_t n4 = (size_t)TOK * DIM / 4;
    uint2* dst = (uint2*)g_x;
    const float4* src = (const float4*)x;
    for (; i < n4; i += stride) {
        float4 v = src[i];
        dst[i] = make_uint2(pkh2(v.x, v.y), pkh2(v.z, v.w));
    }
}

// ======================================================================
// Kernel A: h = silu(X@W1) * (X@W3). CTA: 256m x 64n (dual B), 256 thr.
// 8 warps 4m x 2n; warp tile 64m x 32n per GEMM. grid = 64*16 = 1024.
// ======================================================================
__global__ __launch_bounds__(256, 1)
void moe_up_kernel(const float* __restrict__ w1,
                   const float* __restrict__ w3)
{
    extern __shared__ __align__(1024) char smem[];
    const uint32_t sbase = smem_u32(smem);
    const int tid  = threadIdx.x;
    const int lane = tid & 31;
    const int wid  = tid >> 5;
    const int bid  = blockIdx.x;
    const int e    = bid >> 4;
    const int nt   = bid & 15;

    const __half* xb = g_x + (size_t)(e * TPE) * DIM;
    const float* w1b = w1 + (size_t)e * DIM * HID + nt * 64;
    const float* w3b = w3 + (size_t)e * DIM * HID + nt * 64;

    const int wm = wid >> 1, wn = wid & 1;
    const int mbase = wm * 64, nbase = wn * 32;
    const int blk = lane >> 3, r = lane & 7;

    const int am = tid >> 3, aq = tid & 7;     // A rows am + j*32, j<8
    const int nb = tid & 63, kq = tid >> 6;    // B: n row, k-octs kq, kq+4

    auto cpA = [&](int s) {
        const uint32_t buf = sbase + (uint32_t)(s & 3) * ABUF_SZ;
        const int k0 = s * 64;
        #pragma unroll
        for (int j = 0; j < 8; j++) {
            int m = am + j * 32;
            cp16(buf + SWZ(m * 128 + aq * 16), xb + (size_t)m * DIM + k0 + aq * 8);
        }
    };
    float v1[2][8], v3[2][8];
    auto ldgB = [&](int s) {
        #pragma unroll
        for (int j = 0; j < 2; j++) {
            const int k0 = s * 64 + (kq + j * 4) * 8;
            #pragma unroll
            for (int t = 0; t < 8; t++) {
                v1[j][t] = w1b[(size_t)(k0 + t) * HID + nb];
                v3[j][t] = w3b[(size_t)(k0 + t) * HID + nb];
            }
        }
    };
    auto stsB = [&](int s) {
        char* buf = smem + BOFF + (size_t)(s & 3) * BSTG;
        #pragma unroll
        for (int j = 0; j < 2; j++) {
            int ch = kq + j * 4;
            uint4 t1 = { pkh2(v1[j][0], v1[j][1]), pkh2(v1[j][2], v1[j][3]),
                         pkh2(v1[j][4], v1[j][5]), pkh2(v1[j][6], v1[j][7]) };
            *(uint4*)(buf + nb * 144 + ch * 16) = t1;
            uint4 t3 = { pkh2(v3[j][0], v3[j][1]), pkh2(v3[j][2], v3[j][3]),
                         pkh2(v3[j][4], v3[j][5]), pkh2(v3[j][6], v3[j][7]) };
            *(uint4*)(buf + 9216 + nb * 144 + ch * 16) = t3;
        }
    };

    float acc1[4][4][4], acc3[4][4][4];
    #pragma unroll
    for (int i = 0; i < 4; i++)
        #pragma unroll
        for (int j = 0; j < 4; j++)
            #pragma unroll
            for (int k = 0; k < 4; k++) { acc1[i][j][k] = 0.f; acc3[i][j][k] = 0.f; }

    ldgB(0); stsB(0);
    ldgB(1); stsB(1);
    ldgB(2);
    cpA(0); CP_COMMIT();
    cpA(1); CP_COMMIT();
    cpA(2); CP_COMMIT();

    const int q = lane >> 3, rr = lane & 7;
    const uint32_t brel = (uint32_t)((q & 1) * 8 + rr) * 144 + (uint32_t)(q >> 1) * 16
                        + (uint32_t)nbase * 144;

    const int NS = DIM / 64;   // 32
    #pragma unroll 1
    for (int s = 0; s < NS; s++) {
        CP_WAIT2();
        __syncthreads();
        const uint32_t aA  = sbase + (uint32_t)(s & 3) * ABUF_SZ;
        const uint32_t aB1 = sbase + BOFF + (uint32_t)(s & 3) * BSTG + brel;
        const uint32_t aB3 = aB1 + 9216;
        #pragma unroll
        for (int kk = 0; kk < 4; kk++) {
            uint32_t af[4][4];
            #pragma unroll
            for (int m2 = 0; m2 < 4; m2++)
                ldsm4(af[m2], aA + SWZ((mbase + m2 * 16 + (blk & 1) * 8 + r) * 128 + kk * 32 + (blk >> 1) * 16));
            uint32_t bf1[2][4], bf3[2][4];
            #pragma unroll
            for (int j = 0; j < 2; j++) {
                ldsm4(bf1[j], aB1 + j * 2304 + kk * 32);
                ldsm4(bf3[j], aB3 + j * 2304 + kk * 32);
            }
            #pragma unroll
            for (int m2 = 0; m2 < 4; m2++)
                #pragma unroll
                for (int j = 0; j < 2; j++)
                    #pragma unroll
                    for (int pp = 0; pp < 2; pp++) {
                        mma16(acc1[m2][j * 2 + pp], af[m2], bf1[j][pp], bf1[j][pp + 2]);
                        mma16(acc3[m2][j * 2 + pp], af[m2], bf3[j][pp], bf3[j][pp + 2]);
                    }
        }
        if (s + 2 < NS) stsB(s + 2);
        if (s + 3 < NS) { ldgB(s + 3); cpA(s + 3); }
        CP_COMMIT();
    }

    // fused SwiGLU epilogue -> g_h (fp16)
    const int g = lane >> 2, t4 = lane & 3;
    __half* hb = g_h + (size_t)(e * TPE) * HID + nt * 64;
    #pragma unroll
    for (int m2 = 0; m2 < 4; m2++) {
        #pragma unroll
        for (int p = 0; p < 4; p++) {
            int row = mbase + m2 * 16 + g;
            int col = nbase + p * 8 + 2 * t4;
            *(uint32_t*)(hb + (size_t)row * HID + col) =
                pkh2(silu(acc1[m2][p][0]) * acc3[m2][p][0],
                     silu(acc1[m2][p][1]) * acc3[m2][p][1]);
            *(uint32_t*)(hb + (size_t)(row + 8) * HID + col) =
                pkh2(silu(acc1[m2][p][2]) * acc3[m2][p][2],
                     silu(acc1[m2][p][3]) * acc3[m2][p][3]);
        }
    }
}

// ======================================================================
// Kernel B: out = h @ W2. CTA: 256m x 128n, 256 thr.
// 8 warps 4m x 2n; warp tile 64m x 64n. grid = 64*16 = 1024.
// ======================================================================
__global__ __launch_bounds__(256, 1)
void moe_down_kernel(const float* __restrict__ w2, float* __restrict__ out)
{
    extern __shared__ __align__(1024) char smem[];
    const uint32_t sbase = smem_u32(smem);
    const int tid  = threadIdx.x;
    const int lane = tid & 31;
    const int wid  = tid >> 5;
    const int bid  = blockIdx.x;
    const int e    = bid >> 4;
    const int nt   = bid & 15;

    const __half* hb = g_h + (size_t)(e * TPE) * HID;
    const float* w2b = w2 + (size_t)e * HID * DIM + nt * 128;

    const int wm = wid >> 1, wn = wid & 1;
    const int mbase = wm * 64, nbase = wn * 64;
    const int blk = lane >> 3, r = lane & 7;

    const int am = tid >> 3, aq = tid & 7;     // A rows am + j*32, j<8
    const int nb = tid & 127, kg = tid >> 7;   // B: n row, k-octs kg+2j

    auto cpA = [&](int s) {
        const uint32_t buf = sbase + (uint32_t)(s & 3) * ABUF_SZ;
        const int k0 = s * 64;
        #pragma unroll
        for (int j = 0; j < 8; j++) {
            int m = am + j * 32;
            cp16(buf + SWZ(m * 128 + aq * 16), hb + (size_t)m * HID + k0 + aq * 8);
        }
    };
    float vB[4][8];
    auto ldgB = [&](int s) {
        #pragma unroll
        for (int j = 0; j < 4; j++) {
            const int k0 = s * 64 + (kg + j * 2) * 8;
            #pragma unroll
            for (int t = 0; t < 8; t++)
                vB[j][t] = w2b[(size_t)(k0 + t) * DIM + nb];
        }
    };
    auto stsB = [&](int s) {
        char* buf = smem + BOFF + (size_t)(s & 3) * BSTG;
        #pragma unroll
        for (int j = 0; j < 4; j++) {
            int ch = kg + j * 2;
            uint4 t = { pkh2(vB[j][0], vB[j][1]), pkh2(vB[j][2], vB[j][3]),
                        pkh2(vB[j][4], vB[j][5]), pkh2(vB[j][6], vB[j][7]) };
            *(uint4*)(buf + nb * 144 + ch * 16) = t;
        }
    };

    float acc[4][8][4];
    #pragma unroll
    for (int i = 0; i < 4; i++)
        #pragma unroll
        for (int j = 0; j < 8; j++)
            #pragma unroll
            for (int k = 0; k < 4; k++) acc[i][j][k] = 0.f;

    ldgB(0); stsB(0);
    ldgB(1); stsB(1);
    ldgB(2);
    cpA(0); CP_COMMIT();
    cpA(1); CP_COMMIT();
    cpA(2); CP_COMMIT();

    const int q = lane >> 3, rr = lane & 7;
    const uint32_t brel = (uint32_t)((q & 1) * 8 + rr) * 144 + (uint32_t)(q >> 1) * 16
                        + (uint32_t)nbase * 144;

    const int NS = HID / 64;   // 16
    #pragma unroll 1
    for (int s = 0; s < NS; s++) {
        CP_WAIT2();
        __syncthreads();
        const uint32_t aA = sbase + (uint32_t)(s & 3) * ABUF_SZ;
        const uint32_t aB = sbase + BOFF + (uint32_t)(s & 3) * BSTG + brel;
        #pragma unroll
        for (int kk = 0; kk < 4; kk++) {
            uint32_t af[4][4];
            #pragma unroll
            for (int m2 = 0; m2 < 4; m2++)
                ldsm4(af[m2], aA + SWZ((mbase + m2 * 16 + (blk & 1) * 8 + r) * 128 + kk * 32 + (blk >> 1) * 16));
            uint32_t bf[4][4];
            #pragma unroll
            for (int j = 0; j < 4; j++)
                ldsm4(bf[j], aB + j * 2304 + kk * 32);
            #pragma unroll
            for (int m2 = 0; m2 < 4; m2++)
                #pragma unroll
                for (int j = 0; j < 4; j++)
                    #pragma unroll
                    for (int pp = 0; pp < 2; pp++)
                        mma16(acc[m2][j * 2 + pp], af[m2], bf[j][pp], bf[j][pp + 2]);
        }
        if (s + 2 < NS) stsB(s + 2);
        if (s + 3 < NS) { ldgB(s + 3); cpA(s + 3); }
        CP_COMMIT();
    }

    const int g = lane >> 2, t4 = lane & 3;
    float* ob = out + (size_t)(e * TPE) * DIM + nt * 128;
    #pragma unroll
    for (int m2 = 0; m2 < 4; m2++) {
        #pragma unroll
        for (int p = 0; p < 8; p++) {
            int row = mbase + m2 * 16 + g;
            int col = nbase + p * 8 + 2 * t4;
            float* r0 = ob + (size_t)row * DIM + col;
            float* r1p = r0 + 8 * DIM;
            *(float2*)r0 = make_float2(acc[m2][p][0], acc[m2][p][1]);
            *(float2*)r1p = make_float2(acc[m2][p][2], acc[m2][p][3]);
        }
    }
}

// ======================================================================
extern "C" void kernel_launch(void* const* d_in, const int* in_sizes, int n_in,
                              void* d_out, int out_size)
{
    (void)in_sizes; (void)n_in; (void)out_size;
    const float* x  = (const float*)d_in[0];
    const float* w1 = (const float*)d_in[1];
    const float* w2 = (const float*)d_in[2];
    const float* w3 = (const float*)d_in[3];
    float* out = (float*)d_out;

    static bool attr_set = false;
    if (!attr_set) {
        cudaFuncSetAttribute(moe_up_kernel,   cudaFuncAttributeMaxDynamicSharedMemorySize, SMEM_TOT);
        cudaFuncSetAttribute(moe_down_kernel, cudaFuncAttributeMaxDynamicSharedMemorySize, SMEM_TOT);
        attr_set = true;
    }

    preconv_kernel<<<2048, 256>>>(x);
    moe_up_kernel<<<NEXP * 16, 256, SMEM_TOT>>>(w1, w3);
    moe_down_kernel<<<NEXP * 16, 256, SMEM_TOT>>>(w2, out);
}